// round 15
// baseline (speedup 1.0000x reference)
#include <cuda_runtime.h>
#include <cuda_fp16.h>
#include <cstdint>

#define N_PTS 200000
#define CDIM 96
#define FDIM 96
#define NCOLS 3
#define HDIM 288          // NCOLS * FDIM
#define EPSV 1e-3f

// ---------------- scratch (device globals: no allocation allowed) ----------
__device__ __half g_Z [(size_t)N_PTS * HDIM];  // stage-1 GEMM out (fp16)
__device__ __half g_Zh[(size_t)N_PTS * HDIM];  // stage-2 GEMM out (fp16)
__device__ int   g_prev[NCOLS * N_PTS];
__device__ int   g_next[NCOLS * N_PTS];
// A operands in fp16 (hi only — dropped low terms are ~2^-11 relative)
__device__ __half g_Xh[(size_t)N_PTS * CDIM];
__device__ __half g_hh[(size_t)N_PTS * HDIM];
// fp16 weights, MMA layout: B[n][k]  (n = tap*FDIM + f)
__device__ __half g_B1h[HDIM * CDIM];
__device__ __half g_B2h[HDIM * HDIM];

// ======================= helpers ==========================================
__device__ __forceinline__ uint32_t smem_u32(const void* p) {
    uint32_t a;
    asm("{ .reg .u64 t; cvta.to.shared.u64 t, %1; cvt.u32.u64 %0, t; }"
        : "=r"(a) : "l"(p));
    return a;
}
// .cg: bypass L1 (keep L1 free for ldmatrix traffic)
__device__ __forceinline__ void cp16(uint32_t dst, const void* src) {
    asm volatile("cp.async.cg.shared.global [%0], [%1], 16;"
                 :: "r"(dst), "l"(src) : "memory");
}
__device__ __forceinline__ void cp16p(uint32_t dst, const void* src, uint32_t sz) {
    asm volatile("cp.async.cg.shared.global [%0], [%1], 16, %2;"
                 :: "r"(dst), "l"(src), "r"(sz) : "memory");
}
#define CP_COMMIT() asm volatile("cp.async.commit_group;" ::: "memory")

__device__ __forceinline__ void ldm_x4(uint32_t* r, uint32_t addr) {
    asm volatile("ldmatrix.sync.aligned.m8n8.x4.shared.b16 {%0,%1,%2,%3}, [%4];"
                 : "=r"(r[0]), "=r"(r[1]), "=r"(r[2]), "=r"(r[3]) : "r"(addr));
}

// D += A*B  (m16n8k16, fp16 in, fp32 acc)
__device__ __forceinline__ void mma_f16(float* d, const uint32_t* a,
                                        const uint32_t* b) {
    asm volatile(
        "mma.sync.aligned.m16n8k16.row.col.f32.f16.f16.f32 "
        "{%0,%1,%2,%3}, {%4,%5,%6,%7}, {%8,%9}, {%0,%1,%2,%3};"
        : "+f"(d[0]), "+f"(d[1]), "+f"(d[2]), "+f"(d[3])
        : "r"(a[0]), "r"(a[1]), "r"(a[2]), "r"(a[3]), "r"(b[0]), "r"(b[1]));
}

// f16x2 word -> float2 (exact)
__device__ __forceinline__ float2 up2(uint32_t u) {
    __half2 h = *reinterpret_cast<__half2*>(&u);
    return __half22float2(h);
}

// ---------------- convert X to fp16 -----------------------------------------
__global__ void split_x_kernel(const float* __restrict__ X) {
    int idx = blockIdx.x * 256 + threadIdx.x;        // groups of 4 floats
    if (idx >= N_PTS * (CDIM / 4)) return;
    float4 v = ((const float4*)X)[idx];
    __half2 h0 = __floats2half2_rn(v.x, v.y);
    __half2 h1 = __floats2half2_rn(v.z, v.w);
    ((uint2*)g_Xh)[idx] = make_uint2(*(uint32_t*)&h0, *(uint32_t*)&h1);
}

// ---------------- pack weights: fp16, [n][k] MMA layout --------------------
__global__ void pack_w_kernel(const float* __restrict__ W1,
                              const float* __restrict__ W2) {
    int t = blockIdx.x * blockDim.x + threadIdx.x;
    if (t < HDIM * HDIM) {                       // W2: (3, 288, 96)
        int n = t / HDIM, k = t % HDIM;
        int tap = n / FDIM, f = n % FDIM;
        g_B2h[(size_t)n * HDIM + k] =
            __float2half_rn(W2[((size_t)tap * HDIM + k) * FDIM + f]);
    }
    if (t < HDIM * CDIM) {                       // W1: (3, 96, 96)
        int n = t / CDIM, k = t % CDIM;
        int tap = n / FDIM, f = n % FDIM;
        g_B1h[(size_t)n * CDIM + k] =
            __float2half_rn(W1[((size_t)tap * CDIM + k) * FDIM + f]);
    }
}

// ---------------- neighbor maps --------------------------------------------
__global__ void prevnext_kernel(const int* __restrict__ index) {
    int t = blockIdx.x * blockDim.x + threadIdx.x;
    if (t >= NCOLS * N_PTS) return;
    int i = t / NCOLS;
    int c = t % NCOLS;
    int p = index[t];
    g_prev[c * N_PTS + p] = (i > 0)         ? index[t - NCOLS] : -1;
    g_next[c * N_PTS + p] = (i < N_PTS - 1) ? index[t + NCOLS] : -1;
}

// ============ fp16 HMMA GEMM:  C[M,288] = Ah[M,K] @ Bh[288,K]^T ============
// PERSISTENT CTAs: each CTA loops over tiles; cp.async ring runs across
// tile boundaries (prefetch next tile's chunk during last chunk compute,
// epilogue overlaps next tile's loads). BK=96.
// CTA tile: BM=128, BN=96. 12 warps 4(M) x 3(N); warp tile 32x32.
// Tile decode N-fastest -> concurrent tile window shares A rows in L2.
// Row stride 208B (192B data + 16B pad; conflict-free ldmatrix phases).
#define N_MTILE  1563                // ceil(200000/128)
#define N_TILES  (3 * N_MTILE)       // 4689
#define NTHR     384
#define RSTRIDE  208
#define ABYTES   (128 * RSTRIDE)     // 26624
#define BUF_SZ   ((128 + 96) * RSTRIDE)   // 46592
#define GSM_TOTAL (2 * BUF_SZ)       // 93184 -> 2 CTAs/SM

template <int KDIM>
__device__ __forceinline__ void gemm_stage(
        int tid, int tile, int k0, int buf,
        const __half* __restrict__ Ahp,
        const __half* __restrict__ Bhp,
        uint32_t sb) {
    const int row0 = (tile / 3) * 128;
    const int col0 = (tile % 3) * 96;
    uint32_t base = sb + buf * BUF_SZ;
    // A: 128 rows x 96 k fp16 = 12 x 16B chunks/row -> 1536 tasks
    for (int idx = tid; idx < 1536; idx += NTHR) {
        int r = idx / 12, c = idx - (idx / 12) * 12;
        int gr = row0 + r;
        uint32_t sz = (gr < N_PTS) ? 16u : 0u;
        cp16p(base + (uint32_t)(r * RSTRIDE + c * 16),
              Ahp + (size_t)gr * KDIM + k0 + c * 8, sz);
    }
    // B: 96 rows x 96 k -> 1152 tasks
    for (int idx = tid; idx < 1152; idx += NTHR) {
        int r = idx / 12, c = idx - (idx / 12) * 12;
        size_t go = (size_t)(col0 + r) * KDIM + k0 + c * 8;
        cp16(base + ABYTES + (uint32_t)(r * RSTRIDE + c * 16), Bhp + go);
    }
}

template <int STAGE>
__global__ __launch_bounds__(NTHR, 2)
void mma_gemm_kernel() {
    constexpr int KDIM = (STAGE == 1) ? CDIM : HDIM;
    constexpr int NCH  = KDIM / 96;              // 1 or 3
    const __half* __restrict__ Ahp = (STAGE == 1) ? g_Xh : g_hh;
    const __half* __restrict__ Bhp = (STAGE == 1) ? g_B1h : g_B2h;
    __half* __restrict__ C = (STAGE == 1) ? g_Z : g_Zh;

    extern __shared__ char smem[];
    const uint32_t sb = smem_u32(smem);

    const int tid  = threadIdx.x;
    const int wid  = tid >> 5;
    const int lane = tid & 31;
    const int g    = lane >> 2;        // 0..7
    const int tg   = lane & 3;         // 0..3
    const int wm   = wid & 3;          // M warp 0..3
    const int wn   = wid >> 2;         // N warp 0..2
    const int G    = gridDim.x;        // persistent CTA count

    // ldmatrix lane addressing (byte offsets within a buffer)
    const uint32_t a_lrow = (uint32_t)(wm * 32 + (lane & 15));
    const uint32_t a_loff = a_lrow * RSTRIDE + ((lane >> 4) * 16);
    const uint32_t b_lrow = (uint32_t)(wn * 32 + (lane & 7) + (((lane >> 4) & 1) * 8));
    const uint32_t b_loff = b_lrow * RSTRIDE + (((lane >> 3) & 1) * 16);

    int t0 = blockIdx.x;
    if (t0 >= N_TILES) return;

    // prime the ring: chunk 0 of first tile
    gemm_stage<KDIM>(tid, t0, 0, 0, Ahp, Bhp, sb);
    CP_COMMIT();
    int ci = 0;                        // global chunk counter (ring parity)

    for (int t = t0; t < N_TILES; t += G) {
        const int row0 = (t / 3) * 128;
        const int col0 = (t % 3) * 96;

        float acc[2][4][4];
        #pragma unroll
        for (int mf = 0; mf < 2; mf++)
            #pragma unroll
            for (int nf = 0; nf < 4; nf++)
                #pragma unroll
                for (int i = 0; i < 4; i++) acc[mf][nf][i] = 0.f;

        for (int kc = 0; kc < NCH; kc++) {
            // prefetch next chunk in the global stream
            int nt, nk0;
            if (kc + 1 < NCH) { nt = t; nk0 = (kc + 1) * 96; }
            else              { nt = t + G; nk0 = 0; }
            if (nt < N_TILES) {
                gemm_stage<KDIM>(tid, nt, nk0, (ci + 1) & 1, Ahp, Bhp, sb);
                CP_COMMIT();
                asm volatile("cp.async.wait_group 1;" ::: "memory");
            } else {
                asm volatile("cp.async.wait_group 0;" ::: "memory");
            }
            __syncthreads();

            const uint32_t base = sb + (ci & 1) * BUF_SZ;

            #pragma unroll
            for (int ks = 0; ks < 6; ks++) {      // 6 k16 steps per 96-chunk
                const uint32_t kb = ks * 32;
                uint32_t AH[2][4];
                #pragma unroll
                for (int mf = 0; mf < 2; mf++)
                    ldm_x4(AH[mf], base + a_loff + mf * (16 * RSTRIDE) + kb);
                #pragma unroll
                for (int pnf = 0; pnf < 2; pnf++) {
                    uint32_t bd = base + ABYTES + b_loff + pnf * (16 * RSTRIDE) + kb;
                    uint32_t BH4[4];
                    ldm_x4(BH4, bd);
                    #pragma unroll
                    for (int half = 0; half < 2; half++) {
                        const uint32_t* bh = BH4 + half * 2;
                        mma_f16(acc[0][pnf * 2 + half], AH[0], bh);
                        mma_f16(acc[1][pnf * 2 + half], AH[1], bh);
                    }
                }
            }
            ci++;
            __syncthreads();           // compute done before ring slot reuse
        }

        // epilogue (overlaps the already-issued next-tile loads)
        #pragma unroll
        for (int mf = 0; mf < 2; mf++) {
            int row = row0 + wm * 32 + mf * 16 + g;
            #pragma unroll
            for (int nf = 0; nf < 4; nf++) {
                int col = col0 + wn * 32 + nf * 8 + 2 * tg;
                if (row < N_PTS) {
                    __half2 v = __floats2half2_rn(acc[mf][nf][0], acc[mf][nf][1]);
                    *(uint32_t*)(C + (size_t)row * HDIM + col) = *(uint32_t*)&v;
                }
                if (row + 8 < N_PTS) {
                    __half2 v = __floats2half2_rn(acc[mf][nf][2], acc[mf][nf][3]);
                    *(uint32_t*)(C + (size_t)(row + 8) * HDIM + col) = *(uint32_t*)&v;
                }
            }
        }
    }
}

// -------- assemble stage 1:  h = relu(b1 + 3 gathered taps) -> fp16 --------
__global__ __launch_bounds__(256)
void assemble1_kernel(const float* __restrict__ b1) {
    int idx = blockIdx.x * 256 + threadIdx.x;      // N_PTS * 72 tasks (4 elems)
    if (idx >= N_PTS * 72) return;
    int p = idx / 72;
    int gidx = idx - p * 72;
    int c = gidx / 24;          // tap 0..2
    int j = gidx - c * 24;      // 4-elem group within 96
    int prev = g_prev[c * N_PTS + p];
    int next = g_next[c * N_PTS + p];
    float4 v = ((const float4*)b1)[j];
    if (prev >= 0) {
        uint2 z = *(const uint2*)(g_Z + (size_t)prev * HDIM + j * 4);
        float2 z0 = up2(z.x), z1 = up2(z.y);
        v.x += z0.x; v.y += z0.y; v.z += z1.x; v.w += z1.y;
    }
    {
        uint2 z = *(const uint2*)(g_Z + (size_t)p * HDIM + FDIM + j * 4);
        float2 z0 = up2(z.x), z1 = up2(z.y);
        v.x += z0.x; v.y += z0.y; v.z += z1.x; v.w += z1.y;
    }
    if (next >= 0) {
        uint2 z = *(const uint2*)(g_Z + (size_t)next * HDIM + 2 * FDIM + j * 4);
        float2 z0 = up2(z.x), z1 = up2(z.y);
        v.x += z0.x; v.y += z0.y; v.z += z1.x; v.w += z1.y;
    }
    __half2 h0 = __floats2half2_rn(fmaxf(v.x, 0.f), fmaxf(v.y, 0.f));
    __half2 h1 = __floats2half2_rn(fmaxf(v.z, 0.f), fmaxf(v.w, 0.f));
    int o = p * 72 + c * 24 + j;                   // uint2 (4-elem) index
    ((uint2*)g_hh)[o] = make_uint2(*(uint32_t*)&h0, *(uint32_t*)&h1);
}

// ------- assemble stage 2 + residual + layernorm (warp per point) ----------
__global__ __launch_bounds__(256)
void assemble2_ln_kernel(const float* __restrict__ b2,
                         const float* __restrict__ gamma,
                         const float* __restrict__ beta,
                         float* __restrict__ out) {
    int p    = (blockIdx.x * 256 + threadIdx.x) >> 5;   // warp per point
    int lane = threadIdx.x & 31;
    float4 xv[3];
    float s = 0.f, q = 0.f;
    if (lane < 24) {
        #pragma unroll
        for (int c = 0; c < 3; c++) {
            int prev = g_prev[c * N_PTS + p];
            int next = g_next[c * N_PTS + p];
            float4 v = ((const float4*)b2)[lane];
            if (prev >= 0) {
                uint2 z = *(const uint2*)(g_Zh + (size_t)prev * HDIM + lane * 4);
                float2 z0 = up2(z.x), z1 = up2(z.y);
                v.x += z0.x; v.y += z0.y; v.z += z1.x; v.w += z1.y;
            }
            {
                uint2 z = *(const uint2*)(g_Zh + (size_t)p * HDIM + FDIM + lane * 4);
                float2 z0 = up2(z.x), z1 = up2(z.y);
                v.x += z0.x; v.y += z0.y; v.z += z1.x; v.w += z1.y;
            }
            if (next >= 0) {
                uint2 z = *(const uint2*)(g_Zh + (size_t)next * HDIM + 2 * FDIM + lane * 4);
                float2 z0 = up2(z.x), z1 = up2(z.y);
                v.x += z0.x; v.y += z0.y; v.z += z1.x; v.w += z1.y;
            }
            int o = p * 72 + c * 24 + lane;
            uint2 hh = ((const uint2*)g_hh)[o];
            float2 a0 = up2(hh.x), a1 = up2(hh.y);
            float4 x;
            x.x = a0.x + fmaxf(v.x, 0.f);
            x.y = a0.y + fmaxf(v.y, 0.f);
            x.z = a1.x + fmaxf(v.z, 0.f);
            x.w = a1.y + fmaxf(v.w, 0.f);
            xv[c] = x;
            s += x.x + x.y + x.z + x.w;
            q += x.x * x.x + x.y * x.y + x.z * x.z + x.w * x.w;
        }
    }
    #pragma unroll
    for (int o = 16; o > 0; o >>= 1) {
        s += __shfl_xor_sync(0xffffffffu, s, o);
        q += __shfl_xor_sync(0xffffffffu, q, o);
    }
    float mu  = s * (1.f / HDIM);
    float var = q * (1.f / HDIM) - mu * mu;
    float r   = rsqrtf(var + EPSV);
    if (lane < 24) {
        #pragma unroll
        for (int c = 0; c < 3; c++) {
            float4 gm = ((const float4*)gamma)[c * 24 + lane];
            float4 bt = ((const float4*)beta)[c * 24 + lane];
            float4 x  = xv[c];
            float4 o4;
            o4.x = (x.x - mu) * r * gm.x + bt.x;
            o4.y = (x.y - mu) * r * gm.y + bt.y;
            o4.z = (x.z - mu) * r * gm.z + bt.z;
            o4.w = (x.w - mu) * r * gm.w + bt.w;
            *(float4*)(out + (size_t)p * HDIM + c * FDIM + lane * 4) = o4;
        }
    }
}

// ---------------- index pass-through tail ----------------------------------
__global__ void copy_index_kernel(const int* __restrict__ index,
                                  float* __restrict__ out, int count) {
    int t = blockIdx.x * blockDim.x + threadIdx.x;
    if (t < count) out[t] = (float)index[t];
}

// ---------------------------------------------------------------------------
extern "C" void kernel_launch(void* const* d_in, const int* in_sizes, int n_in,
                              void* d_out, int out_size) {
    const float* X     = (const float*)d_in[0];
    const int*   index = (const int*)  d_in[1];
    const float* W1    = (const float*)d_in[2];
    const float* b1    = (const float*)d_in[3];
    const float* W2    = (const float*)d_in[4];
    const float* b2    = (const float*)d_in[5];
    const float* gamma = (const float*)d_in[6];
    const float* beta  = (const float*)d_in[7];
    float* out = (float*)d_out;

    cudaFuncSetAttribute(mma_gemm_kernel<1>,
                         cudaFuncAttributeMaxDynamicSharedMemorySize, GSM_TOTAL);
    cudaFuncSetAttribute(mma_gemm_kernel<2>,
                         cudaFuncAttributeMaxDynamicSharedMemorySize, GSM_TOTAL);

    int smCount = 148;
    cudaDeviceGetAttribute(&smCount, cudaDevAttrMultiProcessorCount, 0);
    int gpersist = 2 * smCount;
    if (gpersist > N_TILES) gpersist = N_TILES;

    split_x_kernel<<<(N_PTS * 24 + 255) / 256, 256>>>(X);
    pack_w_kernel<<<(HDIM * HDIM + 255) / 256, 256>>>(W1, W2);
    prevnext_kernel<<<(NCOLS * N_PTS + 255) / 256, 256>>>(index);

    mma_gemm_kernel<1><<<gpersist, NTHR, GSM_TOTAL>>>();  // Z  = Xh @ B1h^T
    assemble1_kernel<<<(N_PTS * 72 + 255) / 256, 256>>>(b1);
    mma_gemm_kernel<2><<<gpersist, NTHR, GSM_TOTAL>>>();  // Zh = hh @ B2h^T
    assemble2_ln_kernel<<<(N_PTS * 32 + 255) / 256, 256>>>(b2, gamma, beta, out);

    int tail = out_size - N_PTS * HDIM;
    if (tail > 0) {
        if (tail > NCOLS * N_PTS) tail = NCOLS * N_PTS;
        copy_index_kernel<<<(tail + 255) / 256, 256>>>(
            index, out + (size_t)N_PTS * HDIM, tail);
    }
}